// round 3
// baseline (speedup 1.0000x reference)
#include <cuda_runtime.h>

#define EPS  1e-6f
#define DD   256     // in_features
#define BM   64      // batch tile
#define BN   32      // K tile
#define DK   32      // depth chunk
#define NIT  (DD / DK)
#define LDX  68      // padded stride for x tile (64 rows)
#define LDP  36      // padded stride for p/a tiles (32 rows)

// packed fp32x2 FMA (Blackwell FFMA2) — only reachable via PTX
__device__ __forceinline__ void ffma2(unsigned long long& d,
                                      unsigned long long a,
                                      unsigned long long b) {
    asm("fma.rn.f32x2 %0, %1, %2, %3;" : "=l"(d) : "l"(a), "l"(b), "l"(d));
}
__device__ __forceinline__ unsigned long long bcast2(float v) {
    unsigned long long r;
    asm("mov.b64 %0, {%1, %1};" : "=l"(r) : "r"(__float_as_uint(v)));
    return r;
}
#define LO32F(u) __uint_as_float((unsigned)(u))
#define HI32F(u) __uint_as_float((unsigned)((u) >> 32))

// Fused hyperbolic MLR logits:
// out[b,k] = lam_k * na_k * asinh( 2*za / ((1-z2)*na_k + EPS) )
// built from xp=<x,p>, xa=<x,a>, x2, p2, <p,a>, ||a||^2 (no [B,K,D] intermediate).
__global__ __launch_bounds__(256)
void hyp_mlr_kernel(const float* __restrict__ x,
                    const float* __restrict__ p,
                    const float* __restrict__ a,
                    float* __restrict__ out, int K)
{
    // double-buffered transposed tiles [d][col]; col XOR-swizzled by d-group
    __shared__ float xs [2][DK][LDX];
    __shared__ float ps [2][DK][LDP];
    __shared__ float as_[2][DK][LDP];
    __shared__ float p2s[BN], pas[BN], na2s[BN], x2s[BM];

    const int tid = threadIdx.x;
    const int b0  = blockIdx.y * BM;
    const int k0  = blockIdx.x * BN;

    // ---------------- per-k stats (32 rows x 8 sub-chunks) -------------------
    {
        const int g   = tid >> 3;   // k row 0..31
        const int sub = tid & 7;    // eighth of D (8 float4s each)
        const float4* prow = (const float4*)(p + (size_t)(k0 + g) * DD) + sub * 8;
        const float4* arow = (const float4*)(a + (size_t)(k0 + g) * DD) + sub * 8;
        float p2 = 0.f, pa = 0.f, na2 = 0.f;
        #pragma unroll
        for (int i = 0; i < 8; i++) {
            float4 pv = prow[i];
            float4 av = arow[i];
            p2  += pv.x*pv.x + pv.y*pv.y + pv.z*pv.z + pv.w*pv.w;
            pa  += pv.x*av.x + pv.y*av.y + pv.z*av.z + pv.w*av.w;
            na2 += av.x*av.x + av.y*av.y + av.z*av.z + av.w*av.w;
        }
        #pragma unroll
        for (int m = 1; m <= 4; m <<= 1) {
            p2  += __shfl_xor_sync(0xffffffffu, p2,  m);
            pa  += __shfl_xor_sync(0xffffffffu, pa,  m);
            na2 += __shfl_xor_sync(0xffffffffu, na2, m);
        }
        if (sub == 0) { p2s[g] = p2; pas[g] = pa; na2s[g] = na2; }
    }
    // ---------------- per-b stats (64 rows x 4 sub-chunks) -------------------
    {
        const int g   = tid >> 2;   // b row 0..63
        const int sub = tid & 3;
        const float4* xrow = (const float4*)(x + (size_t)(b0 + g) * DD) + sub * 16;
        float x2 = 0.f;
        #pragma unroll
        for (int i = 0; i < 16; i++) {
            float4 xv = xrow[i];
            x2 += xv.x*xv.x + xv.y*xv.y + xv.z*xv.z + xv.w*xv.w;
        }
        x2 += __shfl_xor_sync(0xffffffffu, x2, 1);
        x2 += __shfl_xor_sync(0xffffffffu, x2, 2);
        if (sub == 0) x2s[g] = x2;
    }

    // ---------------- dual GEMM mainloop (FFMA2, double-buffered) ------------
    unsigned long long accp2[4] = {}, acca2[4] = {};   // 4 x-rows, packed 2 k-cols
    const int ty = tid >> 4;   // 0..15 -> 4 batch rows each
    const int tx = tid & 15;   // 0..15 -> 2 k cols each

    // stage chunk 0
    float4 gx[2], gp, ga;
    {
        const int rx0 = tid >> 2, cx0 = tid & 3;          // x: f=tid   -> row, d-grp (v=0)
        const int rx1 = (256 + tid) >> 3 /*unused*/;
        (void)rx1;
        #pragma unroll
        for (int v = 0; v < 2; v++) {
            int f = v * 256 + tid, row = f >> 3, c4 = f & 7;
            gx[v] = *(const float4*)(x + (size_t)(b0 + row) * DD + c4 * 4);
        }
        int rowp = tid >> 3, c4p = tid & 7;
        gp = *(const float4*)(p + (size_t)(k0 + rowp) * DD + c4p * 4);
        ga = *(const float4*)(a + (size_t)(k0 + rowp) * DD + c4p * 4);
        (void)rx0; (void)cx0;
    }
    // store chunk 0 -> buffer 0 (transposed + swizzled)
    #pragma unroll
    for (int v = 0; v < 2; v++) {
        int f = v * 256 + tid, row = f >> 3, c4 = f & 7;
        int col = (((row >> 2) ^ c4) << 2) | (row & 3);
        float* s = &xs[0][c4 * 4][0];
        s[0 * LDX + col] = gx[v].x; s[1 * LDX + col] = gx[v].y;
        s[2 * LDX + col] = gx[v].z; s[3 * LDX + col] = gx[v].w;
    }
    {
        int row = tid >> 3, c4 = tid & 7;
        int col = (((row >> 2) ^ c4) << 2) | (row & 3);
        ps [0][c4*4+0][col] = gp.x; ps [0][c4*4+1][col] = gp.y;
        ps [0][c4*4+2][col] = gp.z; ps [0][c4*4+3][col] = gp.w;
        as_[0][c4*4+0][col] = ga.x; as_[0][c4*4+1][col] = ga.y;
        as_[0][c4*4+2][col] = ga.z; as_[0][c4*4+3][col] = ga.w;
    }
    __syncthreads();

    for (int it = 0; it < NIT; it++) {
        const int cur = it & 1;

        // prefetch next chunk into regs (overlaps with compute below)
        if (it + 1 < NIT) {
            int d0n = (it + 1) * DK;
            #pragma unroll
            for (int v = 0; v < 2; v++) {
                int f = v * 256 + tid, row = f >> 3, c4 = f & 7;
                gx[v] = *(const float4*)(x + (size_t)(b0 + row) * DD + d0n + c4 * 4);
            }
            int rowp = tid >> 3, c4p = tid & 7;
            gp = *(const float4*)(p + (size_t)(k0 + rowp) * DD + d0n + c4p * 4);
            ga = *(const float4*)(a + (size_t)(k0 + rowp) * DD + d0n + c4p * 4);
        }

        #pragma unroll
        for (int kk = 0; kk < DK; kk++) {
            const int sk = kk >> 2;
            float4 xf = *(const float4*)&xs[cur][kk][(ty ^ sk) << 2];
            int colp = ((((tx >> 1) ^ sk) << 2) | ((tx & 1) << 1));
            unsigned long long pf = *(const unsigned long long*)&ps [cur][kk][colp];
            unsigned long long af = *(const unsigned long long*)&as_[cur][kk][colp];
            unsigned long long xb[4];
            xb[0] = bcast2(xf.x); xb[1] = bcast2(xf.y);
            xb[2] = bcast2(xf.z); xb[3] = bcast2(xf.w);
            #pragma unroll
            for (int i = 0; i < 4; i++) {
                ffma2(accp2[i], xb[i], pf);
                ffma2(acca2[i], xb[i], af);
            }
        }

        // store next chunk into the other buffer, single barrier per iter
        if (it + 1 < NIT) {
            const int nxt = cur ^ 1;
            #pragma unroll
            for (int v = 0; v < 2; v++) {
                int f = v * 256 + tid, row = f >> 3, c4 = f & 7;
                int col = (((row >> 2) ^ c4) << 2) | (row & 3);
                float* s = &xs[nxt][c4 * 4][0];
                s[0 * LDX + col] = gx[v].x; s[1 * LDX + col] = gx[v].y;
                s[2 * LDX + col] = gx[v].z; s[3 * LDX + col] = gx[v].w;
            }
            int row = tid >> 3, c4 = tid & 7;
            int col = (((row >> 2) ^ c4) << 2) | (row & 3);
            ps [nxt][c4*4+0][col] = gp.x; ps [nxt][c4*4+1][col] = gp.y;
            ps [nxt][c4*4+2][col] = gp.z; ps [nxt][c4*4+3][col] = gp.w;
            as_[nxt][c4*4+0][col] = ga.x; as_[nxt][c4*4+1][col] = ga.y;
            as_[nxt][c4*4+2][col] = ga.z; as_[nxt][c4*4+3][col] = ga.w;
            __syncthreads();
        }
    }

    // ---------------- epilogue: hyperbolic MLR logit -------------------------
    #pragma unroll
    for (int i = 0; i < 4; i++) {
        int   b  = b0 + ty * 4 + i;
        float x2 = x2s[ty * 4 + i];
        float xpv[2] = { LO32F(accp2[i]), HI32F(accp2[i]) };
        float xav[2] = { LO32F(acca2[i]), HI32F(acca2[i]) };
        float2 res;
        float* r = (float*)&res;
        #pragma unroll
        for (int j = 0; j < 2; j++) {
            int   kc  = tx * 2 + j;
            float p2  = p2s[kc];
            float pa  = pas[kc];
            float na2 = na2s[kc];
            float xp  = xpv[j];
            float xa  = xav[j];

            float beta  = 1.f - p2;                       // 1 - ||p||^2
            float alpha = -(1.f - 2.f * xp + x2);         // -(1+2uv+v2)
            float den   = 1.f - 2.f * xp + p2 * x2 + EPS; // mobius denom + eps
            float inv   = 1.f / den;
            float z2 = (alpha*alpha*p2 + 2.f*alpha*beta*xp + beta*beta*x2) * inv * inv;
            float za = beta * (alpha * pa + beta * xa) * inv;  // <z, a_pt>
            float na = beta * sqrtf(na2);                       // ||a_pt||
            float lam = 2.f / (beta + EPS);                     // conformal factor
            float t = 2.f * za / ((1.f - z2) * na + EPS);
            r[j] = lam * na * asinhf(t);
        }
        *(float2*)(out + (size_t)b * K + k0 + tx * 2) = res;
    }
}

extern "C" void kernel_launch(void* const* d_in, const int* in_sizes, int n_in,
                              void* d_out, int out_size)
{
    const float* x = (const float*)d_in[0];
    const float* p = (const float*)d_in[1];
    const float* a = (const float*)d_in[2];
    float* out = (float*)d_out;

    const int B = in_sizes[0] / DD;   // 512
    const int K = in_sizes[1] / DD;   // 1024

    dim3 grid(K / BN, B / BM);        // (32, 8) = 256 blocks, 2 CTAs/SM
    hyp_mlr_kernel<<<grid, 256>>>(x, p, a, out, K);
}

// round 4
// speedup vs baseline: 1.1606x; 1.1606x over previous
#include <cuda_runtime.h>

#define EPS  1e-6f
#define DD   256     // in_features
#define BM   64      // batch tile
#define BN   64      // K tile
#define DK   16      // depth chunk
#define NIT  (DD / DK)
#define LDT  68      // padded stride of transposed tiles [d][col]

// packed fp32x2 FMA (Blackwell FFMA2) — only reachable via PTX
__device__ __forceinline__ void ffma2(unsigned long long& d,
                                      unsigned long long a,
                                      unsigned long long b) {
    asm("fma.rn.f32x2 %0, %1, %2, %3;" : "=l"(d) : "l"(a), "l"(b), "l"(d));
}
__device__ __forceinline__ unsigned long long bcast2(float v) {
    unsigned long long r;
    asm("mov.b64 %0, {%1, %1};" : "=l"(r) : "r"(__float_as_uint(v)));
    return r;
}
#define LO32F(u) __uint_as_float((unsigned)(u))
#define HI32F(u) __uint_as_float((unsigned)((u) >> 32))

// Fused hyperbolic MLR logits:
// out[b,k] = lam_k * na_k * asinh( 2*za / ((1-z2)*na_k + EPS) )
// built from xp=<x,p>, xa=<x,a>, x2, p2, <p,a>, ||a||^2 (no [B,K,D] intermediate).
__global__ __launch_bounds__(256, 1)
void hyp_mlr_kernel(const float* __restrict__ x,
                    const float* __restrict__ p,
                    const float* __restrict__ a,
                    float* __restrict__ out, int K)
{
    // double-buffered transposed tiles [d][col]; col = row ^ ((d>>2&3)<<2)
    __shared__ float xs [2][DK][LDT];
    __shared__ float ps [2][DK][LDT];
    __shared__ float as_[2][DK][LDT];
    __shared__ float p2s[BN], pas[BN], na2s[BN], x2s[BM];

    const int tid = threadIdx.x;
    const int b0  = blockIdx.y * BM;
    const int k0  = blockIdx.x * BN;

    // ---------------- per-k stats -------------------------------------------
    {
        const int g   = tid >> 2;   // row 0..63 (k or b)
        const int sub = tid & 3;    // quarter of D
        const float4* prow = (const float4*)(p + (size_t)(k0 + g) * DD) + sub * 16;
        const float4* arow = (const float4*)(a + (size_t)(k0 + g) * DD) + sub * 16;
        float p2 = 0.f, pa = 0.f, na2 = 0.f;
        #pragma unroll
        for (int i = 0; i < 16; i++) {
            float4 pv = prow[i];
            float4 av = arow[i];
            p2  += pv.x*pv.x + pv.y*pv.y + pv.z*pv.z + pv.w*pv.w;
            pa  += pv.x*av.x + pv.y*av.y + pv.z*av.z + pv.w*av.w;
            na2 += av.x*av.x + av.y*av.y + av.z*av.z + av.w*av.w;
        }
        p2  += __shfl_xor_sync(0xffffffffu, p2, 1);
        p2  += __shfl_xor_sync(0xffffffffu, p2, 2);
        pa  += __shfl_xor_sync(0xffffffffu, pa, 1);
        pa  += __shfl_xor_sync(0xffffffffu, pa, 2);
        na2 += __shfl_xor_sync(0xffffffffu, na2, 1);
        na2 += __shfl_xor_sync(0xffffffffu, na2, 2);
        if (sub == 0) { p2s[g] = p2; pas[g] = pa; na2s[g] = na2; }

        const float4* xrow = (const float4*)(x + (size_t)(b0 + g) * DD) + sub * 16;
        float x2 = 0.f;
        #pragma unroll
        for (int i = 0; i < 16; i++) {
            float4 xv = xrow[i];
            x2 += xv.x*xv.x + xv.y*xv.y + xv.z*xv.z + xv.w*xv.w;
        }
        x2 += __shfl_xor_sync(0xffffffffu, x2, 1);
        x2 += __shfl_xor_sync(0xffffffffu, x2, 2);
        if (sub == 0) x2s[g] = x2;
    }

    // ---------------- dual GEMM mainloop ------------------------------------
    // thread tile: 8 m-rows (m-pairs packed in ull) x (2 p-cols + 2 a-cols)
    const int ty = tid >> 5;           // 0..7  : m-group, rows 8*ty..+7
    const int tx = tid & 31;           // 0..31 : n-pair, cols 2*tx, 2*tx+1

    // loader indices: one float4 per array per chunk
    const int ld_row = tid >> 2;       // 0..63
    const int ld_c4  = tid & 3;        // 0..3  : d-group of 4
    const int ld_col = ld_row ^ (ld_c4 << 2);   // swizzled physical column

    unsigned long long accp[4][2] = {}, acca[4][2] = {};

    float4 gx, gp, ga;
    gx = *(const float4*)(x + (size_t)(b0 + ld_row) * DD + ld_c4 * 4);
    gp = *(const float4*)(p + (size_t)(k0 + ld_row) * DD + ld_c4 * 4);
    ga = *(const float4*)(a + (size_t)(k0 + ld_row) * DD + ld_c4 * 4);

    // store chunk 0 -> buffer 0 (transposed + swizzled, conflict-free)
    xs [0][ld_c4*4+0][ld_col] = gx.x; xs [0][ld_c4*4+1][ld_col] = gx.y;
    xs [0][ld_c4*4+2][ld_col] = gx.z; xs [0][ld_c4*4+3][ld_col] = gx.w;
    ps [0][ld_c4*4+0][ld_col] = gp.x; ps [0][ld_c4*4+1][ld_col] = gp.y;
    ps [0][ld_c4*4+2][ld_col] = gp.z; ps [0][ld_c4*4+3][ld_col] = gp.w;
    as_[0][ld_c4*4+0][ld_col] = ga.x; as_[0][ld_c4*4+1][ld_col] = ga.y;
    as_[0][ld_c4*4+2][ld_col] = ga.z; as_[0][ld_c4*4+3][ld_col] = ga.w;
    __syncthreads();

    for (int it = 0; it < NIT; it++) {
        const int cur = it & 1;

        if (it + 1 < NIT) {   // prefetch next chunk into regs
            const int d0n = (it + 1) * DK;
            gx = *(const float4*)(x + (size_t)(b0 + ld_row) * DD + d0n + ld_c4 * 4);
            gp = *(const float4*)(p + (size_t)(k0 + ld_row) * DD + d0n + ld_c4 * 4);
            ga = *(const float4*)(a + (size_t)(k0 + ld_row) * DD + d0n + ld_c4 * 4);
        }

        #pragma unroll
        for (int kk = 0; kk < DK; kk++) {
            const int sk = kk & 12;    // swizzle for this d
            // x: two LDS.128, warp-broadcast (all lanes same address)
            ulonglong2 xv0 = *(const ulonglong2*)&xs[cur][kk][(8*ty    ) ^ sk];
            ulonglong2 xv1 = *(const ulonglong2*)&xs[cur][kk][(8*ty + 4) ^ sk];
            // p/a: LDS.64, 2 cols each, per-phase conflict-free
            float2 pf = *(const float2*)&ps [cur][kk][(2*tx) ^ sk];
            float2 af = *(const float2*)&as_[cur][kk][(2*tx) ^ sk];
            unsigned long long pd0 = bcast2(pf.x), pd1 = bcast2(pf.y);
            unsigned long long ad0 = bcast2(af.x), ad1 = bcast2(af.y);
            unsigned long long xq[4] = { xv0.x, xv0.y, xv1.x, xv1.y };
            #pragma unroll
            for (int w = 0; w < 4; w++) {
                ffma2(accp[w][0], xq[w], pd0);
                ffma2(accp[w][1], xq[w], pd1);
                ffma2(acca[w][0], xq[w], ad0);
                ffma2(acca[w][1], xq[w], ad1);
            }
        }

        if (it + 1 < NIT) {   // store prefetched chunk into other buffer
            const int nxt = cur ^ 1;
            xs [nxt][ld_c4*4+0][ld_col] = gx.x; xs [nxt][ld_c4*4+1][ld_col] = gx.y;
            xs [nxt][ld_c4*4+2][ld_col] = gx.z; xs [nxt][ld_c4*4+3][ld_col] = gx.w;
            ps [nxt][ld_c4*4+0][ld_col] = gp.x; ps [nxt][ld_c4*4+1][ld_col] = gp.y;
            ps [nxt][ld_c4*4+2][ld_col] = gp.z; ps [nxt][ld_c4*4+3][ld_col] = gp.w;
            as_[nxt][ld_c4*4+0][ld_col] = ga.x; as_[nxt][ld_c4*4+1][ld_col] = ga.y;
            as_[nxt][ld_c4*4+2][ld_col] = ga.z; as_[nxt][ld_c4*4+3][ld_col] = ga.w;
            __syncthreads();
        }
    }

    // ---------------- epilogue: hyperbolic MLR logit -------------------------
    #pragma unroll
    for (int w = 0; w < 4; w++) {
        #pragma unroll
        for (int h = 0; h < 2; h++) {
            const int m  = 8 * ty + 2 * w + h;
            const float x2 = x2s[m];
            float2 res;
            float* r = (float*)&res;
            #pragma unroll
            for (int j = 0; j < 2; j++) {
                const int kc = 2 * tx + j;
                float xp = h ? HI32F(accp[w][j]) : LO32F(accp[w][j]);
                float xa = h ? HI32F(acca[w][j]) : LO32F(acca[w][j]);
                float p2  = p2s[kc];
                float pa  = pas[kc];
                float na2 = na2s[kc];

                float beta  = 1.f - p2;                       // 1 - ||p||^2
                float alpha = -(1.f - 2.f * xp + x2);         // -(1+2uv+v2)
                float den   = 1.f - 2.f * xp + p2 * x2 + EPS; // mobius denom + eps
                float inv   = 1.f / den;
                float z2 = (alpha*alpha*p2 + 2.f*alpha*beta*xp + beta*beta*x2) * inv * inv;
                float za = beta * (alpha * pa + beta * xa) * inv;  // <z, a_pt>
                float na = beta * sqrtf(na2);                       // ||a_pt||
                float lam = 2.f / (beta + EPS);                     // conformal factor
                float t = 2.f * za / ((1.f - z2) * na + EPS);
                r[j] = lam * na * asinhf(t);
            }
            *(float2*)(out + (size_t)(b0 + m) * K + k0 + 2 * tx) = res;
        }
    }
}

extern "C" void kernel_launch(void* const* d_in, const int* in_sizes, int n_in,
                              void* d_out, int out_size)
{
    const float* x = (const float*)d_in[0];
    const float* p = (const float*)d_in[1];
    const float* a = (const float*)d_in[2];
    float* out = (float*)d_out;

    const int B = in_sizes[0] / DD;   // 512
    const int K = in_sizes[1] / DD;   // 1024

    dim3 grid(K / BN, B / BM);        // (16, 8) = 128 blocks, 1 CTA/SM
    hyp_mlr_kernel<<<grid, 256>>>(x, p, a, out, K);
}

// round 7
// speedup vs baseline: 1.6633x; 1.4332x over previous
#include <cuda_runtime.h>
#include <cuda_bf16.h>
#include <cstdint>

#define EPS  1e-6f
#define BB   512
#define KK   1024
#define DDIM 256

// ---------------- scratch (device globals: allocation-free) -----------------
__device__ __nv_bfloat16 g_xh[BB * DDIM], g_xl[BB * DDIM];
__device__ __nv_bfloat16 g_ph[KK * DDIM], g_pl[KK * DDIM];
__device__ __nv_bfloat16 g_ah[KK * DDIM], g_al[KK * DDIM];
__device__ float g_x2[BB], g_p2[KK], g_pa[KK], g_na2[KK];

// ---------------- helpers ----------------------------------------------------
__device__ __forceinline__ uint32_t smem_u32(const void* p) {
    uint32_t r;
    asm("{ .reg .u64 t; cvta.to.shared.u64 t, %1; cvt.u32.u64 %0, t; }"
        : "=r"(r) : "l"(p));
    return r;
}
__device__ __forceinline__ uint32_t sw128(uint32_t b) { return b ^ ((b >> 3) & 0x70); }

__device__ __forceinline__ void ldsm_x4(uint32_t* r, uint32_t addr) {
    asm volatile("ldmatrix.sync.aligned.m8n8.x4.shared.b16 {%0,%1,%2,%3}, [%4];"
                 : "=r"(r[0]), "=r"(r[1]), "=r"(r[2]), "=r"(r[3]) : "r"(addr));
}
__device__ __forceinline__ void mma_bf16(float* d, const uint32_t* a,
                                         uint32_t b0, uint32_t b1) {
    asm volatile(
        "mma.sync.aligned.m16n8k16.row.col.f32.bf16.bf16.f32 "
        "{%0,%1,%2,%3}, {%4,%5,%6,%7}, {%8,%9}, {%0,%1,%2,%3};"
        : "+f"(d[0]), "+f"(d[1]), "+f"(d[2]), "+f"(d[3])
        : "r"(a[0]), "r"(a[1]), "r"(a[2]), "r"(a[3]), "r"(b0), "r"(b1));
}

// ============================================================================
// Kernel 1: fp32 -> bf16 hi/lo splits + exact fp32 stats. One warp per row.
// ============================================================================
__device__ __forceinline__ uint32_t pack_hi(float f0, float f1,
                                            float& r0, float& r1) {
    __nv_bfloat16 h0 = __float2bfloat16_rn(f0);
    __nv_bfloat16 h1 = __float2bfloat16_rn(f1);
    r0 = f0 - __bfloat162float(h0);
    r1 = f1 - __bfloat162float(h1);
    return (uint32_t)__bfloat16_as_ushort(h0) |
           ((uint32_t)__bfloat16_as_ushort(h1) << 16);
}
__device__ __forceinline__ uint32_t pack_lo(float r0, float r1) {
    return (uint32_t)__bfloat16_as_ushort(__float2bfloat16_rn(r0)) |
           ((uint32_t)__bfloat16_as_ushort(__float2bfloat16_rn(r1)) << 16);
}
__device__ __forceinline__ void split8(const float* f, uint4& hi, uint4& lo) {
    float r[8];
    hi.x = pack_hi(f[0], f[1], r[0], r[1]);
    hi.y = pack_hi(f[2], f[3], r[2], r[3]);
    hi.z = pack_hi(f[4], f[5], r[4], r[5]);
    hi.w = pack_hi(f[6], f[7], r[6], r[7]);
    lo.x = pack_lo(r[0], r[1]); lo.y = pack_lo(r[2], r[3]);
    lo.z = pack_lo(r[4], r[5]); lo.w = pack_lo(r[6], r[7]);
}

__global__ __launch_bounds__(256)
void conv_stats_kernel(const float* __restrict__ x,
                       const float* __restrict__ p,
                       const float* __restrict__ a)
{
    const int w    = blockIdx.x * 8 + (threadIdx.x >> 5);
    const int lane = threadIdx.x & 31;
    if (w < BB) {
        const int r = w;
        float f[8];
        *(float4*)&f[0] = *(const float4*)(x + r * DDIM + lane * 8);
        *(float4*)&f[4] = *(const float4*)(x + r * DDIM + lane * 8 + 4);
        uint4 hi, lo;
        split8(f, hi, lo);
        *(uint4*)(g_xh + r * DDIM + lane * 8) = hi;
        *(uint4*)(g_xl + r * DDIM + lane * 8) = lo;
        float x2 = 0.f;
        #pragma unroll
        for (int i = 0; i < 8; i++) x2 += f[i] * f[i];
        #pragma unroll
        for (int m = 16; m; m >>= 1) x2 += __shfl_xor_sync(~0u, x2, m);
        if (lane == 0) g_x2[r] = x2;
    } else {
        const int r = w - BB;   // p/a row
        float fp[8], fa[8];
        *(float4*)&fp[0] = *(const float4*)(p + r * DDIM + lane * 8);
        *(float4*)&fp[4] = *(const float4*)(p + r * DDIM + lane * 8 + 4);
        *(float4*)&fa[0] = *(const float4*)(a + r * DDIM + lane * 8);
        *(float4*)&fa[4] = *(const float4*)(a + r * DDIM + lane * 8 + 4);
        uint4 hi, lo;
        split8(fp, hi, lo);
        *(uint4*)(g_ph + r * DDIM + lane * 8) = hi;
        *(uint4*)(g_pl + r * DDIM + lane * 8) = lo;
        split8(fa, hi, lo);
        *(uint4*)(g_ah + r * DDIM + lane * 8) = hi;
        *(uint4*)(g_al + r * DDIM + lane * 8) = lo;
        float p2 = 0.f, pa = 0.f, na2 = 0.f;
        #pragma unroll
        for (int i = 0; i < 8; i++) {
            p2 += fp[i] * fp[i]; pa += fp[i] * fa[i]; na2 += fa[i] * fa[i];
        }
        #pragma unroll
        for (int m = 16; m; m >>= 1) {
            p2  += __shfl_xor_sync(~0u, p2,  m);
            pa  += __shfl_xor_sync(~0u, pa,  m);
            na2 += __shfl_xor_sync(~0u, na2, m);
        }
        if (lane == 0) { g_p2[r] = p2; g_pa[r] = pa; g_na2[r] = na2; }
    }
}

// ============================================================================
// Kernel 2: dual split-GEMM via mma.sync bf16 + fused hyperbolic epilogue.
//   CTA: 64(m) x 64(n) tile, 8 warps as 2x4, warp tile 32x16.
//   K-chunks of 32, hi|lo arrays packed into shared 128B rows (SW128).
//   SINGLE smem buffer (24.6KB) + register-staged prefetch -> fits 48KB limit.
// ============================================================================
#define MT   64
#define NT   64
#define KC   32
#define NCH  (DDIM / KC)        // 8
#define PAIR_BYTES 8192         // 64 rows x 128B (hi half | lo half)
#define BUF_BYTES  (3 * PAIR_BYTES)   // X-pair, P-pair, A-pair = 24576

__global__ __launch_bounds__(256, 1)
void hyp_hmma_kernel(float* __restrict__ out)
{
    extern __shared__ char smem[];
    __shared__ float sp2[NT], spa[NT], sna2[NT], sx2[MT];

    const int tid  = threadIdx.x;
    const int wid  = tid >> 5;
    const int lane = tid & 31;
    const int k0   = blockIdx.x * NT;
    const int b0   = blockIdx.y * MT;

    if (tid < NT) {
        sp2[tid]  = g_p2[k0 + tid];
        spa[tid]  = g_pa[k0 + tid];
        sna2[tid] = g_na2[k0 + tid];
    } else if (tid < NT + MT) {
        sx2[tid - NT] = g_x2[b0 + tid - NT];
    }

    // ---- loader setup: 6 arrays, one uint4 per thread per array per chunk --
    const int lrow = tid >> 2;   // 0..63
    const int lseg = tid & 3;    // 0..3 (16B within 64B half-row)
    const __nv_bfloat16* srcs[6] = {
        g_xh + (size_t)b0 * DDIM, g_xl + (size_t)b0 * DDIM,
        g_ph + (size_t)k0 * DDIM, g_pl + (size_t)k0 * DDIM,
        g_ah + (size_t)k0 * DDIM, g_al + (size_t)k0 * DDIM
    };
    uint32_t dstoff[6];
    #pragma unroll
    for (int a = 0; a < 6; a++)
        dstoff[a] = (uint32_t)(a >> 1) * PAIR_BYTES
                  + sw128(lrow * 128 + (a & 1) * 64 + lseg * 16);

    uint4 st[6];
    auto fetch = [&](int c) {
        const int c0 = c * KC;
        #pragma unroll
        for (int a = 0; a < 6; a++)
            st[a] = *(const uint4*)(srcs[a] + (size_t)lrow * DDIM + c0 + lseg * 8);
    };
    auto store = [&]() {
        #pragma unroll
        for (int a = 0; a < 6; a++)
            *(uint4*)(smem + dstoff[a]) = st[a];
    };

    // ---- warp tiling / ldmatrix lane addressing ----------------------------
    const int wm = (wid >> 2) * 32;   // warp m offset
    const int wn = (wid & 3) * 16;    // warp n offset
    const int g  = lane >> 3;         // ldmatrix sub-matrix id
    const int r  = lane & 7;
    const int rowadd = (g & 1) * 8 + r;
    const int coladd = (g >> 1) * 8;  // elements

    const uint32_t smb = smem_u32(smem);

    float accP[2][2][4] = {}, accA[2][2][4] = {};

    fetch(0); store(); __syncthreads();

    for (int c = 0; c < NCH; c++) {
        if (c + 1 < NCH) fetch(c + 1);   // reg prefetch overlaps compute

        #pragma unroll
        for (int ks = 0; ks < 2; ks++) {
            const int kk = ks * 16;
            uint32_t axh[2][4], axl[2][4], bph[4], bpl[4], bah[4], bal[4];
            #pragma unroll
            for (int t = 0; t < 2; t++) {
                uint32_t base = (wm + t * 16 + rowadd) * 128 + (kk + coladd) * 2;
                ldsm_x4(axh[t], smb + sw128(base));
                ldsm_x4(axl[t], smb + sw128(base + 64));
            }
            {
                uint32_t base = (wn + rowadd) * 128 + (kk + coladd) * 2;
                ldsm_x4(bph, smb + PAIR_BYTES     + sw128(base));
                ldsm_x4(bpl, smb + PAIR_BYTES     + sw128(base + 64));
                ldsm_x4(bah, smb + 2 * PAIR_BYTES + sw128(base));
                ldsm_x4(bal, smb + 2 * PAIR_BYTES + sw128(base + 64));
            }
            #pragma unroll
            for (int t = 0; t < 2; t++)
                #pragma unroll
                for (int n = 0; n < 2; n++) {
                    // xp += xh*ph + xl*ph + xh*pl   (ll term dropped, ~2^-16 rel)
                    mma_bf16(accP[t][n], axh[t], bph[n], bph[n + 2]);
                    mma_bf16(accP[t][n], axl[t], bph[n], bph[n + 2]);
                    mma_bf16(accP[t][n], axh[t], bpl[n], bpl[n + 2]);
                    // xa += xh*ah + xl*ah + xh*al
                    mma_bf16(accA[t][n], axh[t], bah[n], bah[n + 2]);
                    mma_bf16(accA[t][n], axl[t], bah[n], bah[n + 2]);
                    mma_bf16(accA[t][n], axh[t], bal[n], bal[n + 2]);
                }
        }

        if (c + 1 < NCH) {
            __syncthreads();   // everyone done reading this chunk
            store();           // overwrite single buffer with next chunk
            __syncthreads();
        }
    }

    // ---- epilogue: hyperbolic MLR logit -------------------------------------
    #pragma unroll
    for (int t = 0; t < 2; t++)
        #pragma unroll
        for (int h = 0; h < 2; h++) {
            const int mloc = wm + t * 16 + h * 8 + (lane >> 2);
            const float x2 = sx2[mloc];
            #pragma unroll
            for (int n = 0; n < 2; n++) {
                const int kloc = wn + n * 8 + (lane & 3) * 2;
                float2 res;
                float* rr = (float*)&res;
                #pragma unroll
                for (int q = 0; q < 2; q++) {
                    const int kc2 = kloc + q;
                    const float xp  = accP[t][n][h * 2 + q];
                    const float xa  = accA[t][n][h * 2 + q];
                    const float p2  = sp2[kc2];
                    const float pa  = spa[kc2];
                    const float na2 = sna2[kc2];

                    float beta  = 1.f - p2;
                    float alpha = -(1.f - 2.f * xp + x2);
                    float den   = 1.f - 2.f * xp + p2 * x2 + EPS;
                    float inv   = 1.f / den;
                    float z2 = (alpha*alpha*p2 + 2.f*alpha*beta*xp + beta*beta*x2)
                               * inv * inv;
                    float za = beta * (alpha * pa + beta * xa) * inv;
                    float na = beta * sqrtf(na2);
                    float lam = 2.f / (beta + EPS);
                    float tt = 2.f * za / ((1.f - z2) * na + EPS);
                    rr[q] = lam * na * asinhf(tt);
                }
                *(float2*)(out + (size_t)(b0 + mloc) * KK + k0 + kloc) = res;
            }
        }
}

// ============================================================================
extern "C" void kernel_launch(void* const* d_in, const int* in_sizes, int n_in,
                              void* d_out, int out_size)
{
    const float* x = (const float*)d_in[0];
    const float* p = (const float*)d_in[1];
    const float* a = (const float*)d_in[2];
    float* out = (float*)d_out;

    conv_stats_kernel<<<(BB + KK) / 8, 256>>>(x, p, a);

    dim3 grid(KK / NT, BB / MT);    // (16, 8) = 128 CTAs, one wave
    hyp_hmma_kernel<<<grid, 256, BUF_BYTES>>>(out);   // 24.6KB dynamic smem
}

// round 8
// speedup vs baseline: 2.1185x; 1.2737x over previous
#include <cuda_runtime.h>
#include <cuda_bf16.h>
#include <cstdint>

#define EPS  1e-6f
#define BB   512
#define KK   1024
#define DDIM 256

// ---------------- scratch (device globals: allocation-free) -----------------
__device__ __nv_bfloat16 g_xh[BB * DDIM], g_xl[BB * DDIM];
__device__ __nv_bfloat16 g_ph[KK * DDIM], g_pl[KK * DDIM];
__device__ __nv_bfloat16 g_ah[KK * DDIM], g_al[KK * DDIM];
__device__ float g_x2[BB], g_p2[KK], g_pa[KK], g_na2[KK];

// ---------------- helpers ----------------------------------------------------
__device__ __forceinline__ uint32_t smem_u32(const void* p) {
    uint32_t r;
    asm("{ .reg .u64 t; cvta.to.shared.u64 t, %1; cvt.u32.u64 %0, t; }"
        : "=r"(r) : "l"(p));
    return r;
}
__device__ __forceinline__ void ldsm_x4(uint32_t* r, uint32_t addr) {
    asm volatile("ldmatrix.sync.aligned.m8n8.x4.shared.b16 {%0,%1,%2,%3}, [%4];"
                 : "=r"(r[0]), "=r"(r[1]), "=r"(r[2]), "=r"(r[3]) : "r"(addr));
}
__device__ __forceinline__ void mma_bf16(float* d, const uint32_t* a,
                                         uint32_t b0, uint32_t b1) {
    asm volatile(
        "mma.sync.aligned.m16n8k16.row.col.f32.bf16.bf16.f32 "
        "{%0,%1,%2,%3}, {%4,%5,%6,%7}, {%8,%9}, {%0,%1,%2,%3};"
        : "+f"(d[0]), "+f"(d[1]), "+f"(d[2]), "+f"(d[3])
        : "r"(a[0]), "r"(a[1]), "r"(a[2]), "r"(a[3]), "r"(b0), "r"(b1));
}
__device__ __forceinline__ void cp16(uint32_t dst, const void* src) {
    asm volatile("cp.async.cg.shared.global [%0], [%1], 16;"
                 :: "r"(dst), "l"(src) : "memory");
}
#define CP_COMMIT() asm volatile("cp.async.commit_group;" ::: "memory")
#define CP_WAIT(n)  asm volatile("cp.async.wait_group %0;" :: "n"(n) : "memory")

// ============================================================================
// Kernel 1: fp32 -> bf16 hi/lo splits + exact fp32 stats. One warp per row.
// ============================================================================
__device__ __forceinline__ uint32_t pack_hi(float f0, float f1,
                                            float& r0, float& r1) {
    __nv_bfloat16 h0 = __float2bfloat16_rn(f0);
    __nv_bfloat16 h1 = __float2bfloat16_rn(f1);
    r0 = f0 - __bfloat162float(h0);
    r1 = f1 - __bfloat162float(h1);
    return (uint32_t)__bfloat16_as_ushort(h0) |
           ((uint32_t)__bfloat16_as_ushort(h1) << 16);
}
__device__ __forceinline__ uint32_t pack_lo(float r0, float r1) {
    return (uint32_t)__bfloat16_as_ushort(__float2bfloat16_rn(r0)) |
           ((uint32_t)__bfloat16_as_ushort(__float2bfloat16_rn(r1)) << 16);
}
__device__ __forceinline__ void split8(const float* f, uint4& hi, uint4& lo) {
    float r[8];
    hi.x = pack_hi(f[0], f[1], r[0], r[1]);
    hi.y = pack_hi(f[2], f[3], r[2], r[3]);
    hi.z = pack_hi(f[4], f[5], r[4], r[5]);
    hi.w = pack_hi(f[6], f[7], r[6], r[7]);
    lo.x = pack_lo(r[0], r[1]); lo.y = pack_lo(r[2], r[3]);
    lo.z = pack_lo(r[4], r[5]); lo.w = pack_lo(r[6], r[7]);
}

__global__ __launch_bounds__(256)
void conv_stats_kernel(const float* __restrict__ x,
                       const float* __restrict__ p,
                       const float* __restrict__ a)
{
    const int w    = blockIdx.x * 8 + (threadIdx.x >> 5);
    const int lane = threadIdx.x & 31;
    if (w < BB) {
        const int r = w;
        float f[8];
        *(float4*)&f[0] = *(const float4*)(x + r * DDIM + lane * 8);
        *(float4*)&f[4] = *(const float4*)(x + r * DDIM + lane * 8 + 4);
        uint4 hi, lo;
        split8(f, hi, lo);
        *(uint4*)(g_xh + r * DDIM + lane * 8) = hi;
        *(uint4*)(g_xl + r * DDIM + lane * 8) = lo;
        float x2 = 0.f;
        #pragma unroll
        for (int i = 0; i < 8; i++) x2 += f[i] * f[i];
        #pragma unroll
        for (int m = 16; m; m >>= 1) x2 += __shfl_xor_sync(~0u, x2, m);
        if (lane == 0) g_x2[r] = x2;
    } else {
        const int r = w - BB;
        float fp[8], fa[8];
        *(float4*)&fp[0] = *(const float4*)(p + r * DDIM + lane * 8);
        *(float4*)&fp[4] = *(const float4*)(p + r * DDIM + lane * 8 + 4);
        *(float4*)&fa[0] = *(const float4*)(a + r * DDIM + lane * 8);
        *(float4*)&fa[4] = *(const float4*)(a + r * DDIM + lane * 8 + 4);
        uint4 hi, lo;
        split8(fp, hi, lo);
        *(uint4*)(g_ph + r * DDIM + lane * 8) = hi;
        *(uint4*)(g_pl + r * DDIM + lane * 8) = lo;
        split8(fa, hi, lo);
        *(uint4*)(g_ah + r * DDIM + lane * 8) = hi;
        *(uint4*)(g_al + r * DDIM + lane * 8) = lo;
        float p2 = 0.f, pa = 0.f, na2 = 0.f;
        #pragma unroll
        for (int i = 0; i < 8; i++) {
            p2 += fp[i] * fp[i]; pa += fp[i] * fa[i]; na2 += fa[i] * fa[i];
        }
        #pragma unroll
        for (int m = 16; m; m >>= 1) {
            p2  += __shfl_xor_sync(~0u, p2,  m);
            pa  += __shfl_xor_sync(~0u, pa,  m);
            na2 += __shfl_xor_sync(~0u, na2, m);
        }
        if (lane == 0) { g_p2[r] = p2; g_pa[r] = pa; g_na2[r] = na2; }
    }
}

// ============================================================================
// Kernel 2: dual split-GEMM (mma.sync bf16) with cp.async 2-stage pipeline.
//   CTA: 64(m) x 32(n), 8 warps as 4x2, warp tile 16x16. 2 CTAs/SM, one wave.
//   Stage = X-pair(8K) + P-pair(4K) + A-pair(4K) = 16KB; 2 stages = 32KB.
//   Row layout: 128B = hi k32 (64B) | lo k32 (64B); swizzle: col ^ ((row&7)<<4).
// ============================================================================
#define MT    64
#define NT    32
#define KC    32
#define NCH   (DDIM / KC)   // 8
#define STAGE 16384
#define XOFF  0
#define POFF  8192
#define AOFF  12288
#define SMEM2 (2 * STAGE + (3 * NT + MT) * 4)

__global__ __launch_bounds__(256, 2)
void hyp_hmma_kernel(float* __restrict__ out)
{
    extern __shared__ char smem[];
    const uint32_t smb = smem_u32(smem);

    float* sp2  = (float*)(smem + 2 * STAGE);
    float* spa  = sp2 + NT;
    float* sna2 = spa + NT;
    float* sx2  = sna2 + NT;

    const int tid  = threadIdx.x;
    const int wid  = tid >> 5;
    const int lane = tid & 31;
    const int k0   = blockIdx.x * NT;
    const int b0   = blockIdx.y * MT;

    if (tid < NT) {
        sp2[tid]  = g_p2[k0 + tid];
        spa[tid]  = g_pa[k0 + tid];
        sna2[tid] = g_na2[k0 + tid];
    } else if (tid < NT + MT) {
        sx2[tid - NT] = g_x2[b0 + tid - NT];
    }

    // ---- cp.async loader: 4x 16B per thread per chunk -----------------------
    const int xrow = tid >> 2, xseg = tid & 3;                 // X: 64 rows
    const int phalf = tid >> 7;                                // P/A hi or lo
    const int prow = (tid & 127) >> 2, pseg = tid & 3;         // 32 rows
    const __nv_bfloat16* xsrc_h = g_xh + (size_t)(b0 + xrow) * DDIM + xseg * 8;
    const __nv_bfloat16* xsrc_l = g_xl + (size_t)(b0 + xrow) * DDIM + xseg * 8;
    const __nv_bfloat16* psrc = (phalf ? g_pl : g_ph) + (size_t)(k0 + prow) * DDIM + pseg * 8;
    const __nv_bfloat16* asrc = (phalf ? g_al : g_ah) + (size_t)(k0 + prow) * DDIM + pseg * 8;
    const uint32_t xdst_h = XOFF + xrow * 128 + ((xseg * 16)      ^ ((xrow & 7) << 4));
    const uint32_t xdst_l = XOFF + xrow * 128 + ((64 + xseg * 16) ^ ((xrow & 7) << 4));
    const uint32_t pdst   = POFF + prow * 128 + ((phalf * 64 + pseg * 16) ^ ((prow & 7) << 4));
    const uint32_t adst   = pdst + (AOFF - POFF);

    auto load_chunk = [&](int stage, int c) {
        const int c0 = c * KC;
        const uint32_t sb = smb + stage * STAGE;
        cp16(sb + xdst_h, xsrc_h + c0);
        cp16(sb + xdst_l, xsrc_l + c0);
        cp16(sb + pdst,   psrc + c0);
        cp16(sb + adst,   asrc + c0);
        CP_COMMIT();
    };

    // ---- warp tiling / ldsm addressing --------------------------------------
    const int wm = (wid >> 1) * 16;          // warp m offset (4 warps)
    const int wn = (wid & 1)  * 16;          // warp n offset (2 warps)
    const int g  = lane >> 3;
    const int r  = lane & 7;
    const int rowadd = (g & 1) * 8 + r;      // 0..15
    const int cadd   = ((g >> 1) * 8) * 2;   // 0 or 16 bytes
    const uint32_t rxor  = (rowadd & 7) << 4;
    const uint32_t xterm = XOFF + (wm + rowadd) * 128;   // (wm,wn mult of 16 -> row&7 = rowadd&7)
    const uint32_t pterm = POFF + (wn + rowadd) * 128;
    const uint32_t aterm = AOFF + (wn + rowadd) * 128;

    float accP[2][4] = {}, accA[2][4] = {};

    load_chunk(0, 0);
    load_chunk(1, 1);

    for (int c = 0; c < NCH; c++) {
        if (c < NCH - 1) CP_WAIT(1); else CP_WAIT(0);
        __syncthreads();

        const uint32_t sb = smb + (c & 1) * STAGE;
        #pragma unroll
        for (int ks = 0; ks < 2; ks++) {
            const uint32_t kb = ks * 32;   // kstep byte offset within 64B half
            uint32_t axh[4], axl[4], bph[4], bpl[4], bah[4], bal[4];
            ldsm_x4(axh, sb + xterm + (((kb + cadd)     ) ^ rxor));
            ldsm_x4(axl, sb + xterm + ((64 + kb + cadd) ^ rxor));
            ldsm_x4(bph, sb + pterm + (((kb + cadd)     ) ^ rxor));
            ldsm_x4(bpl, sb + pterm + ((64 + kb + cadd) ^ rxor));
            ldsm_x4(bah, sb + aterm + (((kb + cadd)     ) ^ rxor));
            ldsm_x4(bal, sb + aterm + ((64 + kb + cadd) ^ rxor));
            #pragma unroll
            for (int n = 0; n < 2; n++) {
                // xp += xh*ph + xl*ph + xh*pl (ll dropped, ~2^-16 rel)
                mma_bf16(accP[n], axh, bph[n], bph[n + 2]);
                mma_bf16(accP[n], axl, bph[n], bph[n + 2]);
                mma_bf16(accP[n], axh, bpl[n], bpl[n + 2]);
                // xa += xh*ah + xl*ah + xh*al
                mma_bf16(accA[n], axh, bah[n], bah[n + 2]);
                mma_bf16(accA[n], axl, bah[n], bah[n + 2]);
                mma_bf16(accA[n], axh, bal[n], bal[n + 2]);
            }
        }

        if (c + 2 < NCH) {
            __syncthreads();               // all warps done reading this stage
            load_chunk(c & 1, c + 2);      // refill it, async
        }
    }

    // ---- epilogue: hyperbolic MLR logit -------------------------------------
    #pragma unroll
    for (int h = 0; h < 2; h++) {
        const int mloc = wm + h * 8 + (lane >> 2);
        const float x2 = sx2[mloc];
        #pragma unroll
        for (int n = 0; n < 2; n++) {
            const int kloc = wn + n * 8 + (lane & 3) * 2;
            float2 res;
            float* rr = (float*)&res;
            #pragma unroll
            for (int q = 0; q < 2; q++) {
                const int kc2 = kloc + q;
                const float xp  = accP[n][h * 2 + q];
                const float xa  = accA[n][h * 2 + q];
                const float p2  = sp2[kc2];
                const float pa  = spa[kc2];
                const float na2 = sna2[kc2];

                float beta  = 1.f - p2;
                float alpha = -(1.f - 2.f * xp + x2);
                float den   = 1.f - 2.f * xp + p2 * x2 + EPS;
                float inv   = 1.f / den;
                float z2 = (alpha*alpha*p2 + 2.f*alpha*beta*xp + beta*beta*x2)
                           * inv * inv;
                float za = beta * (alpha * pa + beta * xa) * inv;
                float na = beta * sqrtf(na2);
                float lam = 2.f / (beta + EPS);
                float tt = 2.f * za / ((1.f - z2) * na + EPS);
                rr[q] = lam * na * asinhf(tt);
            }
            *(float2*)(out + (size_t)(b0 + mloc) * KK + k0 + kloc) = res;
        }
    }
}

// ============================================================================
extern "C" void kernel_launch(void* const* d_in, const int* in_sizes, int n_in,
                              void* d_out, int out_size)
{
    const float* x = (const float*)d_in[0];
    const float* p = (const float*)d_in[1];
    const float* a = (const float*)d_in[2];
    float* out = (float*)d_out;

    conv_stats_kernel<<<(BB + KK) / 8, 256>>>(x, p, a);

    dim3 grid(KK / NT, BB / MT);    // (32, 8) = 256 CTAs, 2/SM, one wave
    hyp_hmma_kernel<<<grid, 256, SMEM2>>>(out);   // 33.4KB dynamic smem
}